// round 12
// baseline (speedup 1.0000x reference)
#include <cuda_runtime.h>
#include <cuda_bf16.h>
#include <cstddef>

#define ROWS   128
#define T      30
#define OUT_T  26
#define NPAIRS 8256
#define NTHREADS 512
#define NWARPS   16
#define UNITS    320        // 10 tiles * 32 i-iterations
#define UPW      (UNITS / NWARPS)   // 20 units per warp

#define XS_STRIDE 36        // 144 B rows: 16B-aligned for float4 broadcast loads
// float2 staging stride: 37 = 5 (mod 16) makes both STS.64 and the gather
// LDS.64 hit the 2-lanes-per-8B-bank floor (13*37 = 481 ≡ 1 mod 16).
#define STG2_STRIDE 37
#define STG2_WORDS (13 * STG2_STRIDE)   // 481 float2 per warp

__device__ __forceinline__ int pair_offset(int i) {
    return i * ROWS - (i * (i - 1)) / 2;
}

__device__ __forceinline__ int div26(int w) {   // exact floor(w/26) for 0<=w<832
    return (w * 10083) >> 18;
}

__global__ __launch_bounds__(NTHREADS, 1)
void ts_cov_kernel(const float* __restrict__ in, float* __restrict__ out) {
    const int batch = blockIdx.x;

    __shared__ float xs[ROWS * XS_STRIDE];            // 18432 B
    __shared__ float2 stage2[NWARPS * STG2_WORDS];    // 61568 B

    float* stage_f = (float*)stage2;

    // ---- Stage raw input (coalesced) ----
    const float* gin = in + (size_t)batch * (ROWS * T);
    for (int idx = threadIdx.x; idx < ROWS * T; idx += NTHREADS)
        stage_f[idx] = gin[idx];
    __syncthreads();

    // ---- Per-row normalization (population std) ----
    if (threadIdx.x < ROWS) {
        const int r = threadIdx.x;
        float s = 0.f;
#pragma unroll
        for (int t = 0; t < T; t++) s += stage_f[r * T + t];
        const float mean = s * (1.0f / T);
        float v = 0.f;
#pragma unroll
        for (int t = 0; t < T; t++) {
            float c = stage_f[r * T + t] - mean;
            v += c * c;
        }
        const float inv = rsqrtf(v * (1.0f / T));
#pragma unroll
        for (int t = 0; t < T; t++)
            xs[r * XS_STRIDE + t] = (stage_f[r * T + t] - mean) * inv;
    }
    __syncthreads();   // xs ready; stage2[] reused as per-warp staging

    const int wid  = threadIdx.x >> 5;
    const int lane = threadIdx.x & 31;
    float2* sw2 = stage2 + wid * STG2_WORDS;
    float* gout = out + (size_t)batch * ((size_t)NPAIRS * OUT_T);

    const int uA = wid * UPW;
    const int uB = uA + UPW;

    for (int tile = (uA >> 5); tile <= ((uB - 1) >> 5); ++tile) {
        // tile -> (jb, is), triangular enumeration with is <= jb
        const int jb = (tile >= 6) ? 3 : (tile >= 3) ? 2 : (tile >= 1) ? 1 : 0;
        const int is = tile - (jb * (jb + 1)) / 2;
        const int j0 = jb * 32;

        // b row (j0+lane) register-resident for this tile (float4 loads)
        float b[T];
        {
            const float4* bp = (const float4*)(xs + (j0 + lane) * XS_STRIDE);
#pragma unroll
            for (int m = 0; m < 7; m++) {
                float4 v4 = bp[m];
                b[m * 4 + 0] = v4.x; b[m * 4 + 1] = v4.y;
                b[m * 4 + 2] = v4.z; b[m * 4 + 3] = v4.w;
            }
            float2 v2 = *(const float2*)(xs + (j0 + lane) * XS_STRIDE + 28);
            b[28] = v2.x; b[29] = v2.y;
        }

        const int loU = max(uA, tile * 32);
        const int hiU = min(uB, tile * 32 + 32);

        for (int u = loU; u < hiU; ++u) {
            const int i = is * 32 + (u - tile * 32);

            // Broadcast-load row i (8 wavefronts), form products
            float p[T];
            {
                const float4* ap = (const float4*)(xs + i * XS_STRIDE);
#pragma unroll
                for (int m = 0; m < 7; m++) {
                    float4 v4 = ap[m];
                    p[m * 4 + 0] = v4.x * b[m * 4 + 0];
                    p[m * 4 + 1] = v4.y * b[m * 4 + 1];
                    p[m * 4 + 2] = v4.z * b[m * 4 + 2];
                    p[m * 4 + 3] = v4.w * b[m * 4 + 3];
                }
                float2 v2 = *(const float2*)(xs + i * XS_STRIDE + 28);
                p[28] = v2.x * b[28];
                p[29] = v2.y * b[29];
            }

            // Parallel window sums (no serial recurrence):
            // d[t] = p[t]+p[t+1];  res[k] = (d[k] + d[k+2] + p[k+4]) / 5
            float d[T - 1];
#pragma unroll
            for (int t = 0; t < T - 1; t++) d[t] = p[t] + p[t + 1];

            // Stage as float2 pairs: sw2[kk*37 + lane] = (res[2kk], res[2kk+1])
#pragma unroll
            for (int kk = 0; kk < 13; kk++) {
                const int k = 2 * kk;
                float e0 = (d[k] + d[k + 2] + p[k + 4]) * 0.2f;
                float e1 = (d[k + 1] + d[k + 3] + p[k + 5]) * 0.2f;
                sw2[kk * STG2_STRIDE + lane] = make_float2(e0, e1);
            }
            __syncwarp();

            // Coalesced copy-out
            const int lo = (i > j0) ? (i - j0) : 0;
            const size_t p_start = (size_t)pair_offset(i) + (size_t)(j0 + lo - i);
            float* basep = gout + p_start * OUT_T;

            if (lo == 0) {
                // full tile: 416 float2; (w,w+1) w even -> sw2[k/2][q], conflict-free
#pragma unroll
                for (int m = 0; m < 13; m++) {
                    const int w = 2 * (m * 32 + lane);
                    const int q = div26(w);
                    const int kk = (w - q * OUT_T) >> 1;
                    *(float2*)(basep + w) = sw2[kk * STG2_STRIDE + q];
                }
            } else {
                const int total = (32 - lo) * OUT_T;
#pragma unroll
                for (int m = 0; m < OUT_T; m++) {
                    const int w = m * 32 + lane;
                    if (w < total) {
                        const int q = div26(w);
                        const int k = w - q * OUT_T;
                        const float2 v = sw2[(k >> 1) * STG2_STRIDE + lo + q];
                        basep[w] = (k & 1) ? v.y : v.x;
                    }
                }
            }
            __syncwarp();   // protect sw2 before next iteration's STS
        }
    }
}

extern "C" void kernel_launch(void* const* d_in, const int* in_sizes, int n_in,
                              void* d_out, int out_size) {
    const float* in = (const float*)d_in[0];
    float* out = (float*)d_out;
    const int B = in_sizes[0] / (ROWS * T);
    ts_cov_kernel<<<B, NTHREADS>>>(in, out);
}